// round 12
// baseline (speedup 1.0000x reference)
#include <cuda_runtime.h>
#include <cuda_fp16.h>
#include <cstdint>

#define B_SZ 1024
#define F_SZ 256
#define D_SZ 64
#define NFULL (F_SZ * D_SZ)      // 16384 output cols
#define GRID_MAIN 128            // N-slices of 128

// ---------------- device scratch ----------------
__device__ float  g_qkv[3 * F_SZ * D_SZ];    // qkv[t][f][d]
__device__ float  g_trans[2 * F_SZ * D_SZ];  // trans[t][f][d]
__device__ float  g_MT[F_SZ * F_SZ];         // MT[j][i] = gated cross (fp32, transposed)
__device__ float  g_SA[B_SZ * F_SZ];         // s0*s2 [b][i]
__device__ __half g_S1h[B_SZ * F_SZ];        // s1[b][j] fp16
__device__ __half g_P[F_SZ * NFULL];         // P[j][i*64+d] = MT[j][i]*Q2[j][d]

// ---------------- smem layout for k_main (bytes) ----------------
#define B_RB 272                  // P-slice row: 128 halfs + 8 pad = 136 h
#define A_RB 528                  // S1 row: 256 halfs + 8 pad = 264 h
#define SM_B 0                    // 256 * 272 = 69632
#define SM_A 69632                // 2 x (128 * 528) = 135168
#define ABUF (128 * A_RB)         // 67584
#define SMEM_TOTAL (SM_A + 2 * ABUF)   // 204800

// ---------------- helpers ----------------
__device__ __forceinline__ uint32_t smem_u32(const void* p) {
    uint32_t a;
    asm("{ .reg .u64 t; cvta.to.shared.u64 t, %1; cvt.u32.u64 %0, t; }"
        : "=r"(a) : "l"(p));
    return a;
}
#define LDSM4(r, a) \
    asm volatile("ldmatrix.sync.aligned.m8n8.x4.shared.b16 {%0,%1,%2,%3}, [%4];" \
                 : "=r"((r)[0]), "=r"((r)[1]), "=r"((r)[2]), "=r"((r)[3]) : "r"(a))
#define LDSM4T(r, a) \
    asm volatile("ldmatrix.sync.aligned.m8n8.x4.trans.shared.b16 {%0,%1,%2,%3}, [%4];" \
                 : "=r"((r)[0]), "=r"((r)[1]), "=r"((r)[2]), "=r"((r)[3]) : "r"(a))
#define HMMA(d, a, b0, b1) \
    asm volatile("mma.sync.aligned.m16n8k16.row.col.f32.f16.f16.f32 " \
                 "{%0,%1,%2,%3}, {%4,%5,%6,%7}, {%8,%9}, {%0,%1,%2,%3};" \
                 : "+f"((d)[0]), "+f"((d)[1]), "+f"((d)[2]), "+f"((d)[3]) \
                 : "r"((a)[0]), "r"((a)[1]), "r"((a)[2]), "r"((a)[3]), \
                   "r"(b0), "r"(b1))
#define CP16(dst, src) \
    asm volatile("cp.async.ca.shared.global [%0], [%1], 16;" \
                 :: "r"(dst), "l"(src))
#define CP_COMMIT() asm volatile("cp.async.commit_group;" ::: "memory")
#define CP_WAIT0()  asm volatile("cp.async.wait_group 0;" ::: "memory")

// ---------------- K1: qkv / trans = indicator @ W ----------------
__global__ void k_qkv(const float* __restrict__ ind,
                      const float* __restrict__ Wqk,
                      const float* __restrict__ Wqkv) {
    int m = blockIdx.y;
    int fl = threadIdx.x >> 6, e = threadIdx.x & 63;
    int f = blockIdx.x * 4 + fl;
    __shared__ float indS[4 * D_SZ];
    indS[threadIdx.x] = ind[f * D_SZ + e];
    __syncthreads();
    const float* W = (m < 3) ? (Wqkv + m * D_SZ * D_SZ)
                             : (Wqk + (m - 3) * D_SZ * D_SZ);
    float acc = 0.f;
#pragma unroll
    for (int d = 0; d < D_SZ; d++) acc = fmaf(indS[fl * 64 + d], W[d * D_SZ + e], acc);
    if (m < 3) g_qkv[m * F_SZ * D_SZ + f * D_SZ + e] = acc;
    else       g_trans[(m - 3) * F_SZ * D_SZ + f * D_SZ + e] = acc;
}

// ---------------- K2: merged gate + s kernel ----------------
// blocks [0,256): gate rows -> g_MT[j][i] (fp32, transposed);
// blocks [256,768): S1h/SA, 2 batches each.
__global__ void __launch_bounds__(256) k_prep(const float* __restrict__ feature) {
    int tid = threadIdx.x, w = tid >> 5, l = tid & 31;
    if (blockIdx.x < 256) {
        int i = blockIdx.x;
        __shared__ float q1i[D_SZ], t0i[D_SZ];
        if (tid < 64) q1i[tid] = g_qkv[F_SZ * D_SZ + i * D_SZ + tid];
        else if (tid < 128) t0i[tid - 64] = g_trans[i * D_SZ + (tid - 64)];
        __syncthreads();
        const float* q0 = g_qkv;
        const float* t1 = g_trans + F_SZ * D_SZ;
        for (int jj = 0; jj < 32; jj++) {
            int j = w * 32 + jj;
            float c  = q1i[l] * q0[j * D_SZ + l] + q1i[l + 32] * q0[j * D_SZ + l + 32];
            float gl = t0i[l] * t1[j * D_SZ + l] + t0i[l + 32] * t1[j * D_SZ + l + 32];
#pragma unroll
            for (int o = 16; o > 0; o >>= 1) {
                c  += __shfl_xor_sync(0xFFFFFFFFu, c, o);
                gl += __shfl_xor_sync(0xFFFFFFFFu, gl, o);
            }
            if (l == 0)
                g_MT[j * F_SZ + i] = (gl > 0.f) ? c : 0.f;
        }
    } else {
        int b0 = (blockIdx.x - 256) * 2;
        int hb = l >> 4, ll = l & 15;
        int b = b0 + hb;
        for (int ii = 0; ii < 32; ii++) {
            int i = w * 32 + ii;
            const float4* qp = (const float4*)(g_qkv + i * D_SZ) + ll;
            float4 q0 = qp[0];
            float4 q1 = qp[(F_SZ * D_SZ) / 4];
            float4 q2 = qp[(2 * F_SZ * D_SZ) / 4];
            float4 f = *((const float4*)(feature + (size_t)b * (F_SZ * D_SZ)
                                         + i * D_SZ) + ll);
            float d0 = f.x * q0.x + f.y * q0.y + f.z * q0.z + f.w * q0.w;
            float d1 = f.x * q1.x + f.y * q1.y + f.z * q1.z + f.w * q1.w;
            float d2 = f.x * q2.x + f.y * q2.y + f.z * q2.z + f.w * q2.w;
#pragma unroll
            for (int o = 8; o > 0; o >>= 1) {
                d0 += __shfl_xor_sync(0xFFFFFFFFu, d0, o);
                d1 += __shfl_xor_sync(0xFFFFFFFFu, d1, o);
                d2 += __shfl_xor_sync(0xFFFFFFFFu, d2, o);
            }
            if (ll == 0) {
                g_S1h[b * F_SZ + i] = __float2half_rn(d1);
                g_SA[b * F_SZ + i] = d0 * d2;
            }
        }
    }
}

// ---------------- K3: build P[j][i*64+d] = MT[j][i] * Q2[j][d] (fp16) ----------------
// grid 256 (one j per block), 256 threads.
__global__ void __launch_bounds__(256) k_P() {
    int j = blockIdx.x, tid = threadIdx.x;
    __shared__ float mt[F_SZ];
    __shared__ float q2r[D_SZ];
    mt[tid] = g_MT[j * F_SZ + tid];
    if (tid < 64) q2r[tid] = g_qkv[2 * F_SZ * D_SZ + j * D_SZ + tid];
    __syncthreads();
    __half2* dst = (__half2*)(g_P + (size_t)j * NFULL);
#pragma unroll
    for (int pass = 0; pass < 32; pass++) {
        int pr = pass * 256 + tid;        // half2 index
        int n = pr * 2;
        int i = n >> 6, d = n & 63;
        float m = mt[i];
        dst[pr] = __floats2half2_rn(m * q2r[d], m * q2r[d + 1]);
    }
}

// ---------------- K4: single big GEMM (1024 x 16384 x 256) ----------------
// CTA c owns N-cols [c*128, c*128+128) (i = 2c, 2c+1). B-slice resident in
// smem; M-loop over 8 tiles of 128 batches, A (S1h) double-buffered cp.async.
// 16 warps: 4m x 4n grid of 32x32 warp tiles.
__global__ void __launch_bounds__(512, 1)
k_main(float* __restrict__ out) {
    extern __shared__ char sm[];
    uint32_t sb = smem_u32(sm);
    int tid = threadIdx.x, w = tid >> 5, lane = tid & 31;
    int c = blockIdx.x;

    // ---- load B slice: P[k=0..255][c*128..+128] ----
    {
        const char* src = (const char*)g_P + (size_t)c * 256;  // row offset below
        for (int idx = tid; idx < 4096; idx += 512) {          // uint4 units
            int row = idx >> 4, seg = idx & 15;
            const uint4* s = (const uint4*)((const char*)g_P
                + ((size_t)row * NFULL + c * 128) * 2 + seg * 16);
            *(uint4*)(sm + SM_B + row * B_RB + seg * 16) = *s;
        }
        (void)src;
    }
    // ---- prefetch A tile 0 (128 rows x 512B) ----
    {
        for (int idx = tid; idx < 4096; idx += 512) {          // 16B chunks
            int row = idx >> 5, seg = idx & 31;
            uint32_t dst = sb + SM_A + row * A_RB + seg * 16;
            const char* s = (const char*)g_S1h + ((size_t)row * F_SZ) * 2 + seg * 16;
            CP16(dst, s);
        }
        CP_COMMIT();
    }
    CP_WAIT0();
    __syncthreads();

    int m0 = (w >> 2) * 32, n0 = (w & 3) * 32;
    int g = lane >> 2, t4 = lane & 3;
    uint32_t aB0 = sb + SM_A + (uint32_t)(m0 + (lane & 15)) * A_RB
                   + (uint32_t)(lane >> 4) * 16;
    uint32_t bB = sb + SM_B + (uint32_t)(lane & 15) * B_RB
                  + (uint32_t)(n0 + 8 * (lane >> 4)) * 2;
    int iw = c * 2 + ((w & 3) >> 1);

    for (int mt = 0; mt < 8; mt++) {
        int cur = mt & 1, nxt = cur ^ 1;
        // prefetch next A tile
        if (mt < 7) {
            for (int idx = tid; idx < 4096; idx += 512) {
                int row = idx >> 5, seg = idx & 31;
                uint32_t dst = sb + SM_A + nxt * ABUF + row * A_RB + seg * 16;
                const char* s = (const char*)g_S1h
                    + ((size_t)((mt + 1) * 128 + row) * F_SZ) * 2 + seg * 16;
                CP16(dst, s);
            }
            CP_COMMIT();
        }

        float acc[8][4];
#pragma unroll
        for (int i = 0; i < 8; i++)
#pragma unroll
            for (int q = 0; q < 4; q++) acc[i][q] = 0.f;

        uint32_t aB = aB0 + (uint32_t)cur * ABUF;
#pragma unroll
        for (int k = 0; k < 16; k++) {
            uint32_t kA = (uint32_t)k * 32;
            uint32_t kB = (uint32_t)k * 16 * B_RB;
            uint32_t a0[4], a1[4], bq0[4], bq1[4];
            LDSM4(a0, aB + kA);
            LDSM4(a1, aB + 16 * A_RB + kA);
            LDSM4T(bq0, bB + kB);
            LDSM4T(bq1, bB + kB + 32);

            HMMA(acc[0], a0, bq0[0], bq0[1]);
            HMMA(acc[1], a0, bq0[2], bq0[3]);
            HMMA(acc[2], a0, bq1[0], bq1[1]);
            HMMA(acc[3], a0, bq1[2], bq1[3]);
            HMMA(acc[4], a1, bq0[0], bq0[1]);
            HMMA(acc[5], a1, bq0[2], bq0[3]);
            HMMA(acc[6], a1, bq1[0], bq1[1]);
            HMMA(acc[7], a1, bq1[2], bq1[3]);
        }

        // ---- epilogue: scale by SA[b, iw], store ----
        int bbase = mt * 128;
#pragma unroll
        for (int mts = 0; mts < 2; mts++) {
            int r0 = m0 + mts * 16 + g;
            int b = bbase + r0;
            float f0 = __ldg(g_SA + (size_t)b * F_SZ + iw);
            float f1 = __ldg(g_SA + (size_t)(b + 8) * F_SZ + iw);
#pragma unroll
            for (int nt = 0; nt < 4; nt++) {
                float* a = acc[mts * 4 + nt];
                int col = c * 128 + n0 + nt * 8 + 2 * t4;
                *(float2*)(out + (size_t)b * NFULL + col) =
                    make_float2(a[0] * f0, a[1] * f0);
                *(float2*)(out + (size_t)(b + 8) * NFULL + col) =
                    make_float2(a[2] * f1, a[3] * f1);
            }
        }
        CP_WAIT0();
        __syncthreads();
    }
}

// ---------------- launch ----------------
extern "C" void kernel_launch(void* const* d_in, const int* in_sizes, int n_in,
                              void* d_out, int out_size) {
    const float *feature = nullptr, *indicator = nullptr;
    const float *Wqk = nullptr, *Wqkv = nullptr;
    for (int k = 0; k < n_in; k++) {
        switch (in_sizes[k]) {
            case B_SZ * F_SZ * D_SZ: feature   = (const float*)d_in[k]; break;
            case F_SZ * D_SZ:        indicator = (const float*)d_in[k]; break;
            case 2 * D_SZ * D_SZ:    Wqk       = (const float*)d_in[k]; break;
            case 3 * D_SZ * D_SZ:    Wqkv      = (const float*)d_in[k]; break;
        }
    }
    float* out = (float*)d_out;

    cudaFuncSetAttribute(k_main, cudaFuncAttributeMaxDynamicSharedMemorySize,
                         SMEM_TOTAL);

    k_qkv<<<dim3(64, 5), 256>>>(indicator, Wqk, Wqkv);
    k_prep<<<768, 256>>>(feature);
    k_P<<<256, 256>>>();
    k_main<<<GRID_MAIN, 512, SMEM_TOTAL>>>(out);
}

// round 13
// speedup vs baseline: 1.4728x; 1.4728x over previous
#include <cuda_runtime.h>
#include <cuda_fp16.h>
#include <cstdint>

#define B_SZ 1024
#define F_SZ 256
#define D_SZ 64
#define NFULL (F_SZ * D_SZ)

// ---------------- device scratch ----------------
__device__ float   g_qkv[3 * F_SZ * D_SZ];     // qkv[t][f][d]
__device__ float   g_trans[2 * F_SZ * D_SZ];   // trans[t][f][d]
__device__ __half  g_S1hT[F_SZ * B_SZ];        // S1^T[j][b] fp16
__device__ float   g_SAT[F_SZ * B_SZ];         // (s0*s2)^T[i][b]
__device__ unsigned char g_jl[F_SZ * F_SZ];    // compacted j-lists per i
__device__ float   g_mcf[F_SZ * F_SZ];         // compacted M values per i
__device__ int     g_Kpad[F_SZ];               // padded K per i (mult of 64)

// ---------------- smem layout for k_main (bytes) ----------------
#define PC_RB 144                 // Pc row: 64 halfs + 8 pad
#define A_RB  272                 // A row: 128 halfs + 8 pad
#define SM_JL 0                   // 256 B
#define SM_MC 256                 // 1024 B (fp32)
#define SM_PC 1280                // 256 * 144 = 36864
#define SM_AB 38144               // 2 * 64 * 272 = 34816
#define ABUF  (64 * A_RB)
#define SMEM_TOTAL (SM_AB + 2 * ABUF)   // 72960

// ---------------- helpers ----------------
__device__ __forceinline__ uint32_t smem_u32(const void* p) {
    uint32_t a;
    asm("{ .reg .u64 t; cvta.to.shared.u64 t, %1; cvt.u32.u64 %0, t; }"
        : "=r"(a) : "l"(p));
    return a;
}
#define LDSM4T(r, a) \
    asm volatile("ldmatrix.sync.aligned.m8n8.x4.trans.shared.b16 {%0,%1,%2,%3}, [%4];" \
                 : "=r"((r)[0]), "=r"((r)[1]), "=r"((r)[2]), "=r"((r)[3]) : "r"(a))
#define HMMA4(d, A0, A1, A2, A3, B0, B1) \
    asm volatile("mma.sync.aligned.m16n8k16.row.col.f32.f16.f16.f32 " \
                 "{%0,%1,%2,%3}, {%4,%5,%6,%7}, {%8,%9}, {%0,%1,%2,%3};" \
                 : "+f"((d)[0]), "+f"((d)[1]), "+f"((d)[2]), "+f"((d)[3]) \
                 : "r"(A0), "r"(A1), "r"(A2), "r"(A3), "r"(B0), "r"(B1))
#define CP16(dst, src) \
    asm volatile("cp.async.ca.shared.global [%0], [%1], 16;" \
                 :: "r"(dst), "l"(src))
#define CP_COMMIT() asm volatile("cp.async.commit_group;" ::: "memory")
#define CP_WAIT0()  asm volatile("cp.async.wait_group 0;" ::: "memory")

// ---------------- K1: qkv / trans = indicator @ W ----------------
__global__ void k_qkv(const float* __restrict__ ind,
                      const float* __restrict__ Wqk,
                      const float* __restrict__ Wqkv) {
    int m = blockIdx.y;
    int fl = threadIdx.x >> 6, e = threadIdx.x & 63;
    int f = blockIdx.x * 4 + fl;
    __shared__ float indS[4 * D_SZ];
    indS[threadIdx.x] = ind[f * D_SZ + e];
    __syncthreads();
    const float* W = (m < 3) ? (Wqkv + m * D_SZ * D_SZ)
                             : (Wqk + (m - 3) * D_SZ * D_SZ);
    float acc = 0.f;
#pragma unroll
    for (int d = 0; d < D_SZ; d++) acc = fmaf(indS[fl * 64 + d], W[d * D_SZ + e], acc);
    if (m < 3) g_qkv[m * F_SZ * D_SZ + f * D_SZ + e] = acc;
    else       g_trans[(m - 3) * F_SZ * D_SZ + f * D_SZ + e] = acc;
}

// ---------------- K2: merged gate-compact + s kernel ----------------
// blocks [0,256): gate row i -> compacted jl/mcf/Kpad.
// blocks [256,768): S1hT / SAT, 2 batches each.
__global__ void __launch_bounds__(256) k_prep(const float* __restrict__ feature) {
    int tid = threadIdx.x, w = tid >> 5, l = tid & 31;
    if (blockIdx.x < 256) {
        int i = blockIdx.x;
        __shared__ float rowv[256];
        __shared__ float q1i[D_SZ], t0i[D_SZ];
        __shared__ int woff[8];
        __shared__ int ktot;
        if (tid < 64) q1i[tid] = g_qkv[F_SZ * D_SZ + i * D_SZ + tid];
        else if (tid < 128) t0i[tid - 64] = g_trans[i * D_SZ + (tid - 64)];
        __syncthreads();
        const float* q0 = g_qkv;
        const float* t1 = g_trans + F_SZ * D_SZ;
        for (int jj = 0; jj < 32; jj++) {
            int j = w * 32 + jj;
            float c  = q1i[l] * q0[j * D_SZ + l] + q1i[l + 32] * q0[j * D_SZ + l + 32];
            float gl = t0i[l] * t1[j * D_SZ + l] + t0i[l + 32] * t1[j * D_SZ + l + 32];
#pragma unroll
            for (int o = 16; o > 0; o >>= 1) {
                c  += __shfl_xor_sync(0xFFFFFFFFu, c, o);
                gl += __shfl_xor_sync(0xFFFFFFFFu, gl, o);
            }
            if (l == 0) rowv[j] = (gl > 0.f) ? c : 0.f;
        }
        __syncthreads();
        float v = rowv[tid];
        bool pred = (v != 0.f);
        unsigned bm = __ballot_sync(0xFFFFFFFFu, pred);
        if (l == 0) woff[w] = __popc(bm);
        __syncthreads();
        if (tid == 0) {
            int s = 0;
#pragma unroll
            for (int k = 0; k < 8; k++) { int t = woff[k]; woff[k] = s; s += t; }
            ktot = s;
        }
        __syncthreads();
        int rank = woff[w] + __popc(bm & ((1u << l) - 1u));
        if (pred) {
            g_jl[i * 256 + rank] = (unsigned char)tid;
            g_mcf[i * 256 + rank] = v;
        }
        int K = ktot;
        int Kpad = ((K > 0 ? K : 1) + 63) & ~63;
        if (tid >= K && tid < Kpad) {
            g_jl[i * 256 + tid] = 0;
            g_mcf[i * 256 + tid] = 0.f;
        }
        if (tid == 0) g_Kpad[i] = Kpad;
    } else {
        int b0 = (blockIdx.x - 256) * 2;
        int hb = l >> 4, ll = l & 15;
        int b = b0 + hb;
        for (int ii = 0; ii < 32; ii++) {
            int i = w * 32 + ii;
            const float4* qp = (const float4*)(g_qkv + i * D_SZ) + ll;
            float4 q0 = qp[0];
            float4 q1 = qp[(F_SZ * D_SZ) / 4];
            float4 q2 = qp[(2 * F_SZ * D_SZ) / 4];
            float4 f = *((const float4*)(feature + (size_t)b * (F_SZ * D_SZ)
                                         + i * D_SZ) + ll);
            float d0 = f.x * q0.x + f.y * q0.y + f.z * q0.z + f.w * q0.w;
            float d1 = f.x * q1.x + f.y * q1.y + f.z * q1.z + f.w * q1.w;
            float d2 = f.x * q2.x + f.y * q2.y + f.z * q2.z + f.w * q2.w;
#pragma unroll
            for (int o = 8; o > 0; o >>= 1) {
                d0 += __shfl_xor_sync(0xFFFFFFFFu, d0, o);
                d1 += __shfl_xor_sync(0xFFFFFFFFu, d1, o);
                d2 += __shfl_xor_sync(0xFFFFFFFFu, d2, o);
            }
            if (ll == 0) {
                g_S1hT[i * B_SZ + b] = __float2half_rn(d1);
                g_SAT[i * B_SZ + b] = d0 * d2;
            }
        }
    }
}

// ---------------- K3: gate-sparse GEMM ----------------
// CTA = (i, bhalf): grid 512, 256 threads (8 warps, 4m x 2n of 32x32 tiles).
// Out[b, i*64+d] = SAT[i,b] * sum_k mc[i,k]*S1hT[jl[i,k],b]*q2[jl[i,k],d]
__global__ void __launch_bounds__(256, 3)
k_main(float* __restrict__ out) {
    extern __shared__ char sm[];
    uint32_t sb = smem_u32(sm);
    int tid = threadIdx.x, w = tid >> 5, lane = tid & 31;
    int i = blockIdx.x >> 1, bh = blockIdx.x & 1;

    unsigned char* jl_s = (unsigned char*)(sm + SM_JL);
    float* mc_s = (float*)(sm + SM_MC);

    // load jl + mcf (coalesced)
    if (tid < 64) {
        ((uint32_t*)jl_s)[tid] = ((const uint32_t*)(g_jl + i * 256))[tid];
        ((float4*)mc_s)[tid] = ((const float4*)(g_mcf + i * 256))[tid];
    }
    int Kpad = g_Kpad[i];
    int KC = Kpad >> 6;
    __syncthreads();

    // prefetch A chunk (mt=0, kc=0)
    {
        int mtg = bh * 4;
#pragma unroll
        for (int rep = 0; rep < 4; rep++) {
            int idx = rep * 256 + tid;
            int row = idx >> 4, seg = idx & 15;
            int j = jl_s[row];
            const char* src = (const char*)g_S1hT + (size_t)j * 2048
                              + mtg * 256 + seg * 16;
            CP16(sb + SM_AB + row * A_RB + seg * 16, src);
        }
        CP_COMMIT();
    }

    // build Pc[k][d] = mc[k] * q2[jl[k]][d] (fp16)
    {
        const float4* q2v = (const float4*)(g_qkv + 2 * F_SZ * D_SZ);
        for (int idx = tid; idx < Kpad * 8; idx += 256) {
            int k = idx >> 3, dq = idx & 7;
            int j = jl_s[k];
            float mv = mc_s[k];
            float4 qa = q2v[j * 16 + dq * 2];
            float4 qb = q2v[j * 16 + dq * 2 + 1];
            uint4 v;
            __half2 h;
            h = __floats2half2_rn(qa.x * mv, qa.y * mv); v.x = *(uint32_t*)&h;
            h = __floats2half2_rn(qa.z * mv, qa.w * mv); v.y = *(uint32_t*)&h;
            h = __floats2half2_rn(qb.x * mv, qb.y * mv); v.z = *(uint32_t*)&h;
            h = __floats2half2_rn(qb.z * mv, qb.w * mv); v.w = *(uint32_t*)&h;
            *(uint4*)(sm + SM_PC + k * PC_RB + dq * 16) = v;
        }
    }

    int m0 = (w >> 1) * 32, n0 = (w & 1) * 32;
    int g = lane >> 2, t4 = lane & 3;
    uint32_t aOff = (uint32_t)(lane & 15) * A_RB + (uint32_t)(m0 + 8 * (lane >> 4)) * 2;
    uint32_t bOff = (uint32_t)(lane & 15) * PC_RB + (uint32_t)(n0 + 8 * (lane >> 4)) * 2;

    int buf = 0;
    for (int mt = 0; mt < 4; mt++) {
        int mtg = bh * 4 + mt;
        float acc[8][4];
#pragma unroll
        for (int x = 0; x < 8; x++)
#pragma unroll
            for (int q = 0; q < 4; q++) acc[x][q] = 0.f;

        for (int kc = 0; kc < KC; kc++) {
            CP_WAIT0();
            __syncthreads();
            // prefetch next chunk
            int nkc = kc + 1, nmt = mt;
            if (nkc == KC) { nkc = 0; nmt = mt + 1; }
            if (nmt < 4) {
                int nmtg = bh * 4 + nmt;
                uint32_t abase = sb + SM_AB + (buf ^ 1) * ABUF;
#pragma unroll
                for (int rep = 0; rep < 4; rep++) {
                    int idx = rep * 256 + tid;
                    int row = idx >> 4, seg = idx & 15;
                    int j = jl_s[nkc * 64 + row];
                    const char* src = (const char*)g_S1hT + (size_t)j * 2048
                                      + nmtg * 256 + seg * 16;
                    CP16(abase + row * A_RB + seg * 16, src);
                }
                CP_COMMIT();
            }

            uint32_t aB = sb + SM_AB + buf * ABUF + aOff;
            uint32_t bB = sb + SM_PC + (uint32_t)(kc * 64) * PC_RB + bOff;
#pragma unroll
            for (int kk = 0; kk < 4; kk++) {
                uint32_t aL[4], aH[4], bL[4], bH[4];
                LDSM4T(aL, aB + (uint32_t)(kk * 16) * A_RB);
                LDSM4T(aH, aB + (uint32_t)(kk * 16) * A_RB + 32);
                LDSM4T(bL, bB + (uint32_t)(kk * 16) * PC_RB);
                LDSM4T(bH, bB + (uint32_t)(kk * 16) * PC_RB + 32);
                // A regs from trans load: order (0,2,1,3)
                HMMA4(acc[0], aL[0], aL[2], aL[1], aL[3], bL[0], bL[1]);
                HMMA4(acc[1], aL[0], aL[2], aL[1], aL[3], bL[2], bL[3]);
                HMMA4(acc[2], aL[0], aL[2], aL[1], aL[3], bH[0], bH[1]);
                HMMA4(acc[3], aL[0], aL[2], aL[1], aL[3], bH[2], bH[3]);
                HMMA4(acc[4], aH[0], aH[2], aH[1], aH[3], bL[0], bL[1]);
                HMMA4(acc[5], aH[0], aH[2], aH[1], aH[3], bL[2], bL[3]);
                HMMA4(acc[6], aH[0], aH[2], aH[1], aH[3], bH[0], bH[1]);
                HMMA4(acc[7], aH[0], aH[2], aH[1], aH[3], bH[2], bH[3]);
            }
            buf ^= 1;
        }

        // ---- epilogue ----
        const float* sat = g_SAT + (size_t)i * B_SZ;
#pragma unroll
        for (int part = 0; part < 2; part++) {
            int r0 = m0 + part * 16 + g;
            int b = mtg * 128 + r0;
            float f0 = __ldg(sat + b);
            float f1 = __ldg(sat + b + 8);
#pragma unroll
            for (int nt = 0; nt < 4; nt++) {
                float* a = acc[part * 4 + nt];
                int col = i * 64 + n0 + nt * 8 + 2 * t4;
                *(float2*)(out + (size_t)b * NFULL + col) =
                    make_float2(a[0] * f0, a[1] * f0);
                *(float2*)(out + (size_t)(b + 8) * NFULL + col) =
                    make_float2(a[2] * f1, a[3] * f1);
            }
        }
    }
}

// ---------------- launch ----------------
extern "C" void kernel_launch(void* const* d_in, const int* in_sizes, int n_in,
                              void* d_out, int out_size) {
    const float *feature = nullptr, *indicator = nullptr;
    const float *Wqk = nullptr, *Wqkv = nullptr;
    for (int k = 0; k < n_in; k++) {
        switch (in_sizes[k]) {
            case B_SZ * F_SZ * D_SZ: feature   = (const float*)d_in[k]; break;
            case F_SZ * D_SZ:        indicator = (const float*)d_in[k]; break;
            case 2 * D_SZ * D_SZ:    Wqk       = (const float*)d_in[k]; break;
            case 3 * D_SZ * D_SZ:    Wqkv      = (const float*)d_in[k]; break;
        }
    }
    float* out = (float*)d_out;

    cudaFuncSetAttribute(k_main, cudaFuncAttributeMaxDynamicSharedMemorySize,
                         SMEM_TOTAL);

    k_qkv<<<dim3(64, 5), 256>>>(indicator, Wqk, Wqkv);
    k_prep<<<768, 256>>>(feature);
    k_main<<<512, 256, SMEM_TOTAL>>>(out);
}